// round 9
// baseline (speedup 1.0000x reference)
#include <cuda_runtime.h>
#include <cuda_bf16.h>
#include <math.h>

#define BB 4
#define TT 192
#define LL 120
#define GG 500
#define HH 500      // HL
#define H4 2000
#define H4P 2048
#define KPAD 520    // padded K (bf16 units); 1040B row stride -> LDSM conflict-free
#define NR 480
#define NRP 512
#define OD 24
#define M1 3000
#define M2 1000

// k_lstm tiling: 128 blocks = 32 col-tiles(64 gate-cols) x 4 row-tiles(128 rows)
#define GRIDL 128
#define SWB (64 * KPAD * 2)     // 66560 W_hh stripe bytes
#define SAB (128 * KPAD * 2)    // 133120 h stripe bytes
#define SMEML (SWB + SAB + 16)

// k_gx tiling: 256 blocks = 16 col-tiles(128 cols) x 16 row-tiles(32 rows)
#define GSWB (128 * KPAD * 2)   // 133120 W_ih stripe
#define GSAB (32 * KPAD * 2)    // 33280 H2 stripe
#define SMEMG (GSWB + 2 * GSAB + 16)

// ------------------------- scratch (device globals) -------------------------
__device__ float g_P[KPAD];
__device__ float g_Nv[KPAD];
__device__ __align__(16) float g_bias[H4P];                    // interleaved hc*4+gate
__device__ __align__(16) unsigned short g_WIHh[H4P * KPAD];    // bf16 W_ih [cq][f]
__device__ __align__(16) unsigned short g_Whh[H4P * KPAD];     // bf16 W_hh [cq][k]
__device__ __align__(16) unsigned short g_h2[(size_t)TT * NRP * KPAD];  // bf16 H2 [t][row][f]
__device__ __align__(16) float g_gt[(size_t)TT * GRIDL * 8 * 1024];     // gates fragments
__device__ __align__(16) unsigned short g_h3[3][NRP * KPAD];   // bf16 h ring [row][k]
__device__ __align__(16) float g_c[HH * NRP];                  // c fp32 [hc][row]
__device__ __align__(16) float g_hF[HH * NRP];                 // fp32 h_last [hc][row]
__device__ unsigned g_bar[TT];
__device__ __align__(16) float g_hT[NR * HH];
__device__ __align__(16) float g_z1[NR * M1];
__device__ __align__(16) float g_z2[NR * M2];
__device__ __align__(16) float g_z3[NR * M1];

// ------------------------- helpers -------------------------
__device__ __forceinline__ float fsig(float x) {
    return __fdividef(1.f, 1.f + __expf(-x));
}
__device__ __forceinline__ float ftanh(float x) {
    float ax = fabsf(x);
    float t  = __expf(-2.f * ax);
    float r  = __fdividef(1.f - t, 1.f + t);
    return copysignf(r, x);
}
__device__ __forceinline__ float tf32r(float x) {
    unsigned r;
    asm("cvt.rna.tf32.f32 %0, %1;" : "=r"(r) : "f"(x));
    return __uint_as_float(r);
}
__device__ __forceinline__ unsigned short f2bf(float v) {
    __nv_bfloat16 b = __float2bfloat16_rn(v);
    return *reinterpret_cast<unsigned short*>(&b);
}
__device__ __forceinline__ void cp16(unsigned dst_smem, const void* src) {
    asm volatile("cp.async.cg.shared.global [%0], [%1], 16;" :: "r"(dst_smem), "l"(src));
}
__device__ __forceinline__ void cp_commit() { asm volatile("cp.async.commit_group;"); }
template <int N>
__device__ __forceinline__ void cp_wait() {
    asm volatile("cp.async.wait_group %0;" :: "n"(N));
}
__device__ __forceinline__ void mbar_init(unsigned a, unsigned c) {
    asm volatile("mbarrier.init.shared.b64 [%0], %1;" :: "r"(a), "r"(c) : "memory");
}
__device__ __forceinline__ void mbar_extx(unsigned a, unsigned tx) {
    asm volatile("mbarrier.arrive.expect_tx.shared.b64 _, [%0], %1;" :: "r"(a), "r"(tx) : "memory");
}
__device__ __forceinline__ void mbar_wait(unsigned a, unsigned ph) {
    asm volatile(
        "{\n\t.reg .pred P;\n"
        "W%=:\n\t"
        "mbarrier.try_wait.parity.acquire.cta.shared::cta.b64 P, [%0], %1, 0x989680;\n\t"
        "@P bra D%=;\n\t"
        "bra W%=;\n"
        "D%=:\n\t}"
        :: "r"(a), "r"(ph) : "memory");
}
__device__ __forceinline__ void bulkcp(unsigned dst, const void* src, unsigned bytes, unsigned mbar) {
    asm volatile(
        "cp.async.bulk.shared::cta.global.mbarrier::complete_tx::bytes [%0], [%1], %2, [%3];"
        :: "r"(dst), "l"(src), "r"(bytes), "r"(mbar) : "memory");
}
__device__ __forceinline__ void ldsm4(unsigned* r, unsigned addr) {
    asm volatile("ldmatrix.sync.aligned.m8n8.x4.shared.b16 {%0,%1,%2,%3}, [%4];"
                 : "=r"(r[0]), "=r"(r[1]), "=r"(r[2]), "=r"(r[3]) : "r"(addr));
}
__device__ __forceinline__ void mma16bf(float* d, const unsigned* a, const unsigned* b) {
    asm volatile(
        "mma.sync.aligned.m16n8k16.row.col.f32.bf16.bf16.f32 "
        "{%0,%1,%2,%3}, {%4,%5,%6,%7}, {%8,%9}, {%0,%1,%2,%3};"
        : "+f"(d[0]), "+f"(d[1]), "+f"(d[2]), "+f"(d[3])
        : "r"(a[0]), "r"(a[1]), "r"(a[2]), "r"(a[3]), "r"(b[0]), "r"(b[1]));
}
__device__ __forceinline__ void mma8(float* d, const unsigned* a, const unsigned* b) {
    asm volatile(
        "mma.sync.aligned.m16n8k8.row.col.f32.tf32.tf32.f32 "
        "{%0,%1,%2,%3}, {%4,%5,%6,%7}, {%8,%9}, {%0,%1,%2,%3};"
        : "+f"(d[0]), "+f"(d[1]), "+f"(d[2]), "+f"(d[3])
        : "r"(a[0]), "r"(a[1]), "r"(a[2]), "r"(a[3]), "r"(b[0]), "r"(b[1]));
}

// ------------------------- launch 1: P,N vectors -------------------------
__global__ void k_pn(const float* __restrict__ W1, const float* __restrict__ W2) {
    for (int f = threadIdx.x; f < KPAD; f += 512) {
        float p = 0.f, n = 0.f;
        if (f < GG) {
            for (int g = 0; g < GG; g++) {
                float w = W1[g];
                float v = W2[g * GG + f];
                p = fmaf(fmaxf(w, 0.f), v, p);
                n = fmaf(fmaxf(-w, 0.f), v, n);
            }
        }
        g_P[f]  = p;
        g_Nv[f] = n;
    }
}

// ------------------------- launch 2: weights -> bf16, row-permuted ----------
// grid (H4, 2): y=0 -> W_ih + bias, y=1 -> W_hh. cq = (h%500)*4 + h/500.
__global__ void k_wcvt(const float* __restrict__ W_ih, const float* __restrict__ W_hh,
                       const float* __restrict__ b_ih, const float* __restrict__ b_hh) {
    int h = blockIdx.x;
    int cq = (h % HH) * 4 + h / HH;
    const float* src = blockIdx.y ? (W_hh + (size_t)h * HH) : (W_ih + (size_t)h * GG);
    unsigned short* dst = (blockIdx.y ? g_Whh : g_WIHh) + (size_t)cq * KPAD;
    for (int f = threadIdx.x; f < KPAD; f += 256)
        dst[f] = (f < GG) ? f2bf(src[f]) : (unsigned short)0;
    if (blockIdx.y == 0 && threadIdx.x == 0)
        g_bias[cq] = b_ih[h] + b_hh[h];
}

// ------------------------- launch 3: GCN front -> H2 bf16 -------------------
__global__ void k_front(const float* __restrict__ x, const float* __restrict__ Ahat) {
    __shared__ float xr[LL], sp[LL], sn[LL], su[LL], sv[LL];
    __shared__ float sP[KPAD], sN[KPAD];
    int bid = blockIdx.x;
    int b = bid / TT, t = bid % TT;
    int tid = threadIdx.x;
    for (int f = tid; f < KPAD; f += 256) { sP[f] = g_P[f]; sN[f] = g_Nv[f]; }
    if (tid < LL) xr[tid] = x[(b * TT + t) * LL + tid];
    __syncthreads();
    if (tid < LL) {
        float s = 0.f;
        const float* Ar = &Ahat[tid * LL];
        for (int l = 0; l < LL; l++) s = fmaf(Ar[l], xr[l], s);
        sp[tid] = fmaxf(s, 0.f);
        sn[tid] = fmaxf(-s, 0.f);
    }
    __syncthreads();
    if (tid < LL) {
        float uu = 0.f, vv = 0.f;
        const float* Ar = &Ahat[tid * LL];
        for (int l = 0; l < LL; l++) {
            uu = fmaf(Ar[l], sp[l], uu);
            vv = fmaf(Ar[l], sn[l], vv);
        }
        su[tid] = uu;
        sv[tid] = vv;
    }
    __syncthreads();
    // H2[t][row][f] = relu(u*P + v*N), bf16 pairs
    unsigned* dst = reinterpret_cast<unsigned*>(g_h2);
    for (int e = tid; e < LL * (KPAD / 2); e += 256) {
        int l = e / (KPAD / 2);
        int f2 = (e % (KPAD / 2)) * 2;
        float uu = su[l], vv = sv[l];
        float h0 = fmaxf(fmaf(uu, sP[f2],     vv * sN[f2]),     0.f);
        float h1 = fmaxf(fmaf(uu, sP[f2 + 1], vv * sN[f2 + 1]), 0.f);
        unsigned val = ((unsigned)f2bf(h1) << 16) | (unsigned)f2bf(h0);
        size_t row = (size_t)t * NRP + b * LL + l;
        dst[row * (KPAD / 2) + f2 / 2] = val;
    }
}

// ------------------------- launch 4: zero init -------------------------
__global__ void k_zero() {
    const size_t H3W  = 3ull * NRP * KPAD / 2;        // u32 words of h ring
    const size_t CW   = (size_t)HH * NRP;             // floats of c
    const size_t BARW = TT;
    const size_t PADW = (size_t)TT * (NRP - NR) * (KPAD / 2);  // H2 pad rows (u32)
    const size_t TOTAL = H3W + CW + BARW + PADW;
    size_t stride = (size_t)gridDim.x * 256;
    for (size_t i = (size_t)blockIdx.x * 256 + threadIdx.x; i < TOTAL; i += stride) {
        if (i < H3W) {
            reinterpret_cast<unsigned*>(g_h3)[i] = 0u;
        } else if (i < H3W + CW) {
            g_c[i - H3W] = 0.f;
        } else if (i < H3W + CW + BARW) {
            g_bar[i - H3W - CW] = 0u;
        } else {
            size_t j = i - H3W - CW - BARW;
            size_t per_t = (size_t)(NRP - NR) * (KPAD / 2);
            size_t t = j / per_t;
            size_t rem = j % per_t;
            size_t row = NR + rem / (KPAD / 2);
            size_t w = rem % (KPAD / 2);
            reinterpret_cast<unsigned*>(g_h2)[(t * NRP + row) * (KPAD / 2) + w] = 0u;
        }
    }
}

// ------------------------- launch 5: gates GEMM -> fragments ---------------
// grid (16,16): ct = 128 cols, rt = 32 rows. 256 thr, 8 warps (16 cols each).
__global__ __launch_bounds__(256) void k_gx() {
    extern __shared__ __align__(16) char smc[];
    unsigned smb = (unsigned)__cvta_generic_to_shared(smc);
    unsigned sWb = smb;
    unsigned sA0 = smb + GSWB;
    unsigned mb0 = smb + GSWB + 2 * GSAB;
    int tid = threadIdx.x, warp = tid >> 5, lane = tid & 31;
    int g = lane >> 2, tg = lane & 3;
    int ct = blockIdx.x, rt = blockIdx.y;

    if (tid == 0) { mbar_init(mb0, 1); mbar_init(mb0 + 8, 1); }
    __syncthreads();
    if (tid == 0) {
        mbar_extx(mb0, GSWB + GSAB);
        const unsigned short* wsrc = g_WIHh + (size_t)ct * 128 * KPAD;
        bulkcp(sWb, wsrc, GSWB / 2, mb0);
        bulkcp(sWb + GSWB / 2, (const char*)wsrc + GSWB / 2, GSWB / 2, mb0);
        bulkcp(sA0, g_h2 + ((size_t)0 * NRP + rt * 32) * KPAD, GSAB, mb0);
    }

    int arow = (lane & 7) + ((lane >> 3) & 1) * 8;
    unsigned aR = (unsigned)(arow * (KPAD * 2)) + ((lane >> 4) & 1) * 16;
    int wn = warp * 16 + (lane & 7) + ((lane >> 4) & 1) * 8;
    unsigned wB = sWb + (unsigned)(wn * (KPAD * 2)) + ((lane >> 3) & 1) * 16;

    int c0 = ct * 128 + warp * 16 + 2 * tg;
    float2 bi0 = *(const float2*)&g_bias[c0];
    float2 bi1 = *(const float2*)&g_bias[c0 + 8];

    // mapping to k_lstm fragment coordinates
    int ctl = ct * 2 + (warp >> 2);
    int cwl = warp & 3;
    int rtl = rt >> 2;
    int rgl = (rt >> 1) & 1;
    int milb = (rt & 1) * 2;
    int bxl = rtl * 32 + ctl;
    int tidl = (rgl * 4 + cwl) * 32 + lane;

    #pragma unroll 1
    for (int t = 0; t < TT; t++) {
        if (tid == 0 && t + 1 < TT) {
            unsigned mb = mb0 + ((t + 1) & 1) * 8;
            mbar_extx(mb, GSAB);
            bulkcp(sA0 + ((t + 1) & 1) * GSAB,
                   g_h2 + ((size_t)(t + 1) * NRP + rt * 32) * KPAD, GSAB, mb);
        }
        mbar_wait(mb0 + (t & 1) * 8, (t >> 1) & 1);
        unsigned aB = sA0 + (t & 1) * GSAB;

        float d[2][2][4];
        #pragma unroll
        for (int mi = 0; mi < 2; mi++) {
            d[mi][0][0] = bi0.x; d[mi][0][1] = bi0.y; d[mi][0][2] = bi0.x; d[mi][0][3] = bi0.y;
            d[mi][1][0] = bi1.x; d[mi][1][1] = bi1.y; d[mi][1][2] = bi1.x; d[mi][1][3] = bi1.y;
        }
        #pragma unroll 4
        for (int c16 = 0; c16 < 32; c16++) {
            unsigned kB = (unsigned)(c16 * 32);
            unsigned b4[4], a0[4], a1[4];
            ldsm4(b4, wB + kB);
            ldsm4(a0, aB + aR + kB);
            ldsm4(a1, aB + aR + 16u * (KPAD * 2) + kB);
            mma16bf(d[0][0], a0, b4); mma16bf(d[0][1], a0, b4 + 2);
            mma16bf(d[1][0], a1, b4); mma16bf(d[1][1], a1, b4 + 2);
        }
        size_t base = ((size_t)(t * GRIDL + bxl) * 8) * 1024 + (size_t)tidl * 4;
        #pragma unroll
        for (int mi = 0; mi < 2; mi++)
            #pragma unroll
            for (int ni = 0; ni < 2; ni++) {
                int f = (milb + mi) * 2 + ni;
                *(float4*)&g_gt[base + (size_t)f * 1024] =
                    make_float4(d[mi][ni][0], d[mi][ni][1], d[mi][ni][2], d[mi][ni][3]);
            }
        __syncthreads();
    }
}

// ------------------------- launch 6: persistent LSTM -------------------------
// 128 blocks = 32 ct (64 cols) x 4 rt (128 rows). W_hh stripe resident in smem.
__global__ __launch_bounds__(256) void k_lstm() {
    extern __shared__ __align__(16) char smc[];
    unsigned smb = (unsigned)__cvta_generic_to_shared(smc);
    unsigned sWb = smb, sAb = smb + SWB, mb = smb + SWB + SAB;
    int tid = threadIdx.x, warp = tid >> 5, lane = tid & 31;
    int g = lane >> 2, tg = lane & 3;
    int bx = blockIdx.x, ct = bx & 31, rt = bx >> 5;
    int cw = warp & 3, rg = warp >> 2;
    int R0 = rt * 128;
    int C0w = ct * 64 + cw * 16;

    if (tid == 0) mbar_init(mb, 1);
    // W resident (one-time)
    {
        const char* wsrc = (const char*)(g_Whh + (size_t)ct * 64 * KPAD);
        for (int e = tid * 16; e < SWB; e += 256 * 16)
            cp16(sWb + (unsigned)e, wsrc + e);
        cp_commit(); cp_wait<0>();
    }
    __syncthreads();

    int arow = (lane & 7) + ((lane >> 3) & 1) * 8;
    unsigned akB = ((lane >> 4) & 1) * 16;
    unsigned aAdr[4];
    #pragma unroll
    for (int mi = 0; mi < 4; mi++)
        aAdr[mi] = sAb + (unsigned)((rg * 64 + mi * 16 + arow) * (KPAD * 2)) + akB;
    int wn = cw * 16 + (lane & 7) + ((lane >> 4) & 1) * 8;
    unsigned wB = sWb + (unsigned)(wn * (KPAD * 2)) + ((lane >> 3) & 1) * 16;

    #pragma unroll 1
    for (int t = 0; t < TT; t++) {
        const unsigned short* hin = g_h3[(t + 2) % 3];
        unsigned short* hout = g_h3[t % 3];
        if (tid == 0) {
            mbar_extx(mb, SAB);
            const char* src = (const char*)(hin + (size_t)R0 * KPAD);
            bulkcp(sAb, src, SAB / 2, mb);
            bulkcp(sAb + SAB / 2, src + SAB / 2, SAB / 2, mb);
        }
        // gates fragments (coalesced, overlap with bulk copy)
        float d[4][2][4];
        size_t gb = ((size_t)(t * GRIDL + bx) * 8) * 1024 + (size_t)tid * 4;
        #pragma unroll
        for (int f = 0; f < 8; f++) {
            float4 v = *(const float4*)&g_gt[gb + (size_t)f * 1024];
            d[f >> 1][f & 1][0] = v.x; d[f >> 1][f & 1][1] = v.y;
            d[f >> 1][f & 1][2] = v.z; d[f >> 1][f & 1][3] = v.w;
        }
        mbar_wait(mb, t & 1);

        #pragma unroll 4
        for (int c16 = 0; c16 < 32; c16++) {
            unsigned kB = (unsigned)(c16 * 32);
            unsigned b4[4], a[4][4];
            ldsm4(b4, wB + kB);
            #pragma unroll
            for (int mi = 0; mi < 4; mi++) ldsm4(a[mi], aAdr[mi] + kB);
            #pragma unroll
            for (int mi = 0; mi < 4; mi++) {
                mma16bf(d[mi][0], a[mi], b4);
                mma16bf(d[mi][1], a[mi], b4 + 2);
            }
        }

        // epilogue
        int last = (t == TT - 1);
        #pragma unroll
        for (int mi = 0; mi < 4; mi++) {
            #pragma unroll
            for (int ni = 0; ni < 2; ni++) {
                float d0 = d[mi][ni][0], d1 = d[mi][ni][1];
                float d2 = d[mi][ni][2], d3 = d[mi][ni][3];
                float e0 = __shfl_xor_sync(0xffffffffu, d0, 1);
                float e1 = __shfl_xor_sync(0xffffffffu, d1, 1);
                float e2 = __shfl_xor_sync(0xffffffffu, d2, 1);
                float e3 = __shfl_xor_sync(0xffffffffu, d3, 1);
                if ((lane & 1) == 0) {
                    int c0 = C0w + ni * 8 + 2 * tg;
                    int hc = c0 >> 2;
                    if (hc < HH) {
                        int rA = R0 + rg * 64 + mi * 16 + g;
                        int rB = rA + 8;
                        float cA = g_c[hc * NRP + rA];
                        float ig = fsig(d0), fg = fsig(d1), gg = ftanh(e0), og = fsig(e1);
                        float cn = fmaf(fg, cA, ig * gg);
                        g_c[hc * NRP + rA] = cn;
                        float hv = og * ftanh(cn);
                        hout[(size_t)rA * KPAD + hc] = f2bf(hv);
                        if (last) g_hF[hc * NRP + rA] = hv;
                        float cB = g_c[hc * NRP + rB];
                        ig = fsig(d2); fg = fsig(d3); gg = ftanh(e2); og = fsig(e3);
                        cn = fmaf(fg, cB, ig * gg);
                        g_c[hc * NRP + rB] = cn;
                        hv = og * ftanh(cn);
                        hout[(size_t)rB * KPAD + hc] = f2bf(hv);
                        if (last) g_hF[hc * NRP + rB] = hv;
                    }
                }
            }
        }

        // grid barrier
        __threadfence();
        __syncthreads();
        if (tid == 0) {
            atomicAdd(&g_bar[t], 1u);
            while (*(volatile unsigned*)&g_bar[t] < (unsigned)GRIDL) {}
        }
        __syncthreads();
        __threadfence();
    }
}

// ------------------------- h_last transpose -------------------------
__global__ void k_trh() {
    int idx = blockIdx.x * 256 + threadIdx.x;
    if (idx >= NR * HH) return;
    int n = idx / HH, k = idx % HH;
    g_hT[idx] = g_hF[k * NRP + n];
}

// ------------------------- tf32 MMA GEMM: C = act(A @ W + b) ----------------
__device__ __forceinline__ float* selbuf(int s) {
    switch (s) {
        case 0: return g_hT;
        case 1: return g_z1;
        case 2: return g_z2;
        default: return g_z3;
    }
}

__global__ __launch_bounds__(256) void k_gemmt(int aSel, const float* __restrict__ W,
                                               const float* __restrict__ bias, int cSel,
                                               int M, int K, int N, int doRelu) {
    const float* A = selbuf(aSel);
    float* C = selbuf(cSel);
    __shared__ __align__(16) float As[64 * 36];
    __shared__ __align__(16) float Ws[32 * 72];
    int tid  = threadIdx.x;
    int warp = tid >> 5;
    int lane = tid & 31;
    int g  = lane >> 2;
    int tg = lane & 3;
    int n0 = blockIdx.x * 64, m0 = blockIdx.y * 64;
    int wm = (warp >> 2) * 32;
    int wn = (warp & 3) * 16;

    int ami = tid >> 2;
    int akq = (tid & 3) * 8;
    int wkk = tid >> 3;
    int wnq = (tid & 7) * 8;

    float d[2][2][4];
    #pragma unroll
    for (int i = 0; i < 2; i++)
        #pragma unroll
        for (int j = 0; j < 2; j++)
            #pragma unroll
            for (int q = 0; q < 4; q++) d[i][j][q] = 0.f;

    int nslab = (K + 31) / 32;
    float rA[8], rW[8];

    {
        int m = m0 + ami;
        #pragma unroll
        for (int j = 0; j < 8; j++) {
            int k = akq + j;
            rA[j] = (m < M && k < K) ? A[(size_t)m * K + k] : 0.f;
        }
        #pragma unroll
        for (int j = 0; j < 8; j++) {
            int n = n0 + wnq + j;
            rW[j] = (wkk < K && n < N) ? W[(size_t)wkk * N + n] : 0.f;
        }
    }

    #pragma unroll 1
    for (int s = 0; s < nslab; s++) {
        #pragma unroll
        for (int j = 0; j < 8; j++) As[ami * 36 + akq + j] = tf32r(rA[j]);
        #pragma unroll
        for (int j = 0; j < 8; j++) Ws[wkk * 72 + wnq + j] = tf32r(rW[j]);
        __syncthreads();
        if (s + 1 < nslab) {
            int k0 = (s + 1) * 32;
            int m = m0 + ami;
            #pragma unroll
            for (int j = 0; j < 8; j++) {
                int k = k0 + akq + j;
                rA[j] = (m < M && k < K) ? A[(size_t)m * K + k] : 0.f;
            }
            #pragma unroll
            for (int j = 0; j < 8; j++) {
                int k = k0 + wkk;
                int n = n0 + wnq + j;
                rW[j] = (k < K && n < N) ? W[(size_t)k * N + n] : 0.f;
            }
        }
        const unsigned* Asu = reinterpret_cast<const unsigned*>(As);
        const unsigned* Wsu = reinterpret_cast<const unsigned*>(Ws);
        #pragma unroll
        for (int c8 = 0; c8 < 4; c8++) {
            int kc = c8 * 8;
            unsigned a[2][4], b[2][2];
            #pragma unroll
            for (int mi = 0; mi < 2; mi++) {
                int mbase = (wm + mi * 16 + g) * 36 + kc;
                a[mi][0] = Asu[mbase + tg];
                a[mi][1] = Asu[mbase + 8 * 36 + tg];
                a[mi][2] = Asu[mbase + tg + 4];
                a[mi][3] = Asu[mbase + 8 * 36 + tg + 4];
            }
            #pragma unroll
            for (int ni = 0; ni < 2; ni++) {
                int nb = wn + ni * 8 + g;
                b[ni][0] = Wsu[(kc + tg) * 72 + nb];
                b[ni][1] = Wsu[(kc + tg + 4) * 72 + nb];
            }
            #pragma unroll
            for (int mi = 0; mi < 2; mi++)
                #pragma unroll
                for (int ni = 0; ni < 2; ni++)
                    mma8(d[mi][ni], a[mi], b[ni]);
        }
        __syncthreads();
    }

    #pragma unroll
    for (int mi = 0; mi < 2; mi++) {
        #pragma unroll
        for (int ni = 0; ni < 2; ni++) {
            int mA = m0 + wm + mi * 16 + g;
            int mB = mA + 8;
            int n  = n0 + wn + ni * 8 + 2 * tg;
            float b0 = (n < N)     ? bias[n]     : 0.f;
            float b1 = (n + 1 < N) ? bias[n + 1] : 0.f;
            float v;
            if (mA < M) {
                if (n < N) {
                    v = d[mi][ni][0] + b0;
                    C[(size_t)mA * N + n] = doRelu ? fmaxf(v, 0.f) : v;
                }
                if (n + 1 < N) {
                    v = d[mi][ni][1] + b1;
                    C[(size_t)mA * N + n + 1] = doRelu ? fmaxf(v, 0.f) : v;
                }
            }
            if (mB < M) {
                if (n < N) {
                    v = d[mi][ni][2] + b0;
                    C[(size_t)mB * N + n] = doRelu ? fmaxf(v, 0.f) : v;
                }
                if (n + 1 < N) {
                    v = d[mi][ni][3] + b1;
                    C[(size_t)mB * N + n + 1] = doRelu ? fmaxf(v, 0.f) : v;
                }
            }
        }
    }
}

// ------------------------- final layer -------------------------
__global__ void k_final(const float* __restrict__ Wh4, const float* __restrict__ bh4,
                        float* __restrict__ out) {
    __shared__ float zs[M1];
    int n = blockIdx.x;
    int tid = threadIdx.x;
    for (int k = tid; k < M1; k += 256) zs[k] = g_z3[n * M1 + k];
    __syncthreads();
    int w = tid >> 5, lane = tid & 31;
    #pragma unroll
    for (int oi = 0; oi < 3; oi++) {
        int o = w + oi * 8;
        float p = 0.f;
        for (int k = lane; k < M1; k += 32) p = fmaf(zs[k], Wh4[k * OD + o], p);
        #pragma unroll
        for (int off = 16; off; off >>= 1) p += __shfl_down_sync(0xffffffffu, p, off);
        if (lane == 0) {
            float y = fsig(p + bh4[o]);
            int b = n / LL, l = n % LL;
            out[(b * OD + o) * LL + l] = y;
        }
    }
}

// ------------------------- launcher -------------------------
extern "C" void kernel_launch(void* const* d_in, const int* in_sizes, int n_in,
                              void* d_out, int out_size) {
    const float* x    = (const float*)d_in[0];
    const float* Ahat = (const float*)d_in[1];
    const float* W1   = (const float*)d_in[2];
    const float* W2   = (const float*)d_in[3];
    const float* W_ih = (const float*)d_in[4];
    const float* W_hh = (const float*)d_in[5];
    const float* b_ih = (const float*)d_in[6];
    const float* b_hh = (const float*)d_in[7];
    const float* Wh1  = (const float*)d_in[8];
    const float* bh1  = (const float*)d_in[9];
    const float* Wh2  = (const float*)d_in[10];
    const float* bh2  = (const float*)d_in[11];
    const float* Wh3  = (const float*)d_in[12];
    const float* bh3  = (const float*)d_in[13];
    const float* Wh4  = (const float*)d_in[14];
    const float* bh4  = (const float*)d_in[15];
    float* out = (float*)d_out;

    cudaFuncSetAttribute(k_gx,   cudaFuncAttributeMaxDynamicSharedMemorySize, SMEMG);
    cudaFuncSetAttribute(k_lstm, cudaFuncAttributeMaxDynamicSharedMemorySize, SMEML);

    // launches 1-5 so that k_lstm is launch #6 (ncu -s 5 -c 1 target)
    k_pn<<<1, 512>>>(W1, W2);
    k_wcvt<<<dim3(H4, 2), 256>>>(W_ih, W_hh, b_ih, b_hh);
    k_front<<<BB * TT, 256>>>(x, Ahat);
    k_zero<<<1024, 256>>>();
    k_gx<<<dim3(16, 16), 256, SMEMG>>>();
    k_lstm<<<GRIDL, 256, SMEML>>>();

    k_trh<<<(NR * HH + 255) / 256, 256>>>();
    k_gemmt<<<dim3(47, 8), 256>>>(0, Wh1, bh1, 1, NR, HH, M1, 1);
    k_gemmt<<<dim3(16, 8), 256>>>(1, Wh2, bh2, 2, NR, M1, M2, 1);
    k_gemmt<<<dim3(47, 8), 256>>>(2, Wh3, bh3, 3, NR, M2, M1, 1);
    k_final<<<NR, 256>>>(Wh4, bh4, out);
}